// round 5
// baseline (speedup 1.0000x reference)
#include <cuda_runtime.h>
#include <math.h>

// SpikingLayer T=500, B*N=65536. Two-kernel scheme:
//  K1 (pack): x f32 -> bit-packed g_pk, time-parallel, full occupancy, DRAM-bound.
//  K2 (scan): per-neuron 500-step scan with ZERO input loads in the hot loop;
//     packed words held in registers per 32-step group, static bit tests.
//  Decision logic is bit-identical to the R3 passing kernel:
//    - 2nd-order IIR approximates the 149-tap EPSP conv (~1e-5 abs err)
//    - |u-1| < 1e-3 => recompute with the reference's exact f32 rounding
//      (sum k[j] over set history bits, lag j descending 148..0, f32 adds).

#define TBN 65536
#define T_STEPS 500
#define PADW 8          // leading zero words (history before t=0)
#define NW 16           // ceil(500/32)
#define MARGIN 1e-3f
#define BLK 64

__device__ unsigned g_pk[(PADW + NW) * TBN];   // 6 MB static scratch

// ---------------- K1: pack binary input into bits (+ zero pad) ----------------
__global__ __launch_bounds__(256)
void pack_kernel(const float* __restrict__ x) {
    int tid = blockIdx.x * 256 + threadIdx.x;    // (PADW+NW)*TBN threads
    int n  = tid & (TBN - 1);
    int wq = tid >> 16;
    unsigned acc = 0u;
    if (wq >= PADW) {
        int q = wq - PADW;
        const float* p = x + (size_t)(32 * q) * TBN + n;
        #pragma unroll
        for (int i = 0; i < 32; i++) {
            int t = 32 * q + i;
            if (t < T_STEPS) {
                float xv = __ldcs(p + (size_t)i * TBN);
                acc |= (xv != 0.0f) ? (1u << i) : 0u;
            }
        }
    }
    __stcs(&g_pk[(size_t)wq * TBN + n], acc);
}

// ------------- exact near-threshold recompute (reference rounding) -------------
__device__ __noinline__ float exact_vmem(const unsigned* __restrict__ pk0, int t,
                                         const float* __restrict__ ks) {
    // pk0 points at word q=0 (time 0..31) for this neuron; pad words below.
    float acc = 0.0f;
    #pragma unroll
    for (int w = 4; w >= 0; w--) {           // oldest lag window first
        int e = t - 32 * w;                  // newest time in this window
        int q = e >> 5;                      // arithmetic shift = floor div
        int p = e & 31;
        unsigned lo = __ldg(pk0 + (ptrdiff_t)(q - 1) * TBN);
        unsigned hi = __ldg(pk0 + (ptrdiff_t)q * TBN);
        unsigned W  = __funnelshift_rc(lo, hi, p + 1);  // times e-31..e at bits 0..31
        unsigned m  = __brev(W);             // bit b = x[e - b] = x[t - 32w - b]
        if (w == 4) m &= 0x001FFFFFu;        // lags <= 148
        while (m) {                          // descending bit order (oldest lag first)
            unsigned b = 31u - __clz(m);
            acc += ks[32 * w + b];
            m &= ~(1u << b);
        }
    }
    return acc;
}

// ---------------- K2: per-neuron scan, no input loads in hot loop --------------
template <int CNT>
__device__ __forceinline__ void run_group(
    int g, const unsigned* __restrict__ pk0, float* __restrict__ op,
    const float* __restrict__ ks, float& v1, float& v2, float& r)
{
    const float c1    = 1.7235681711139413f;     // a + b   (a=e^-0.2, b=e^-0.1)
    const float c2    = -0.7408182206817179f;    // -ab = -e^-0.3
    const float A     = 4.5399929762484854e-05f; // a^50 = b^100 = e^-10
    const float alpha = 0.9048374180359595f;     // e^-0.1

    // words covering current bit, lag-50 and lag-100 (pad region handles g<4)
    const unsigned wg   = __ldg(pk0 + (ptrdiff_t)g * TBN);
    const unsigned wgm2 = __ldg(pk0 + (ptrdiff_t)(g - 2) * TBN);
    const unsigned wgm3 = __ldg(pk0 + (ptrdiff_t)(g - 3) * TBN);
    const unsigned wgm4 = __ldg(pk0 + (ptrdiff_t)(g - 4) * TBN);

    const int tbase = 32 * g;
    float* o = op + (size_t)tbase * TBN;

    #pragma unroll
    for (int i = 0; i < CNT; i++) {
        const float xf  = (wg & (1u << i)) ? 1.0f : 0.0f;
        const bool  b50 = (i >= 18) ? ((wgm2 >> (i - 18)) & 1u)
                                    : ((wgm3 >> (i + 14)) & 1u);
        const bool  b100 = (i < 4)  ? ((wgm4 >> (i + 28)) & 1u)
                                    : ((wgm3 >> (i - 4)) & 1u);

        float v = fmaf(c1, v1, fmaf(c2, v2, xf));
        v -= b50  ? A : 0.0f;    // x[t-50]
        v -= b100 ? A : 0.0f;    // x[t-100]
        v2 = v1; v1 = v;

        float u = v + r;
        if (__builtin_expect(fabsf(u - 1.0f) < MARGIN, 0))
            u = exact_vmem(pk0, tbase + i, ks) + r;

        float s = (u >= 1.0f) ? 1.0f : 0.0f;
        r = (r - s) * alpha;
        __stcs(o + (size_t)i * TBN, s);
    }
}

__global__ __launch_bounds__(BLK)
void SpikingLayer_90202903151092_kernel(const float* __restrict__ ker,
                                        float* __restrict__ out) {
    __shared__ float ks[152];
    for (int i = threadIdx.x; i < 149; i += BLK) ks[i] = ker[i];
    __syncthreads();

    const int n = blockIdx.x * BLK + threadIdx.x;
    const unsigned* pk0 = g_pk + (size_t)PADW * TBN + n;   // word q=0
    float* op = out + n;

    float v1 = 0.0f, v2 = 0.0f, r = 0.0f;

    #pragma unroll 1
    for (int g = 0; g < 15; g++)
        run_group<32>(g, pk0, op, ks, v1, v2, r);
    run_group<20>(15, pk0, op, ks, v1, v2, r);   // t = 480..499
}

extern "C" void kernel_launch(void* const* d_in, const int* in_sizes, int n_in,
                              void* d_out, int out_size) {
    const float* x   = (const float*)d_in[0];  // binary_input (500,16,1,4096) f32
    const float* ker = (const float*)d_in[1];  // epsp_kernel (1,149) f32
    float* out = (float*)d_out;                // spikes (500,16,4096) f32
    pack_kernel<<<(PADW + NW) * TBN / 256, 256>>>(x);
    SpikingLayer_90202903151092_kernel<<<TBN / BLK, BLK>>>(ker, out);
}